// round 8
// baseline (speedup 1.0000x reference)
#include <cuda_runtime.h>
#include <cuda_bf16.h>
#include <cstdint>

// ---------------------------------------------------------------------------
// out[t,o] = sum_i (x[t,i]*scales[i]) * W[o,i]
//   x [32,4096] f32, W [14336,4096] int32 (int8-valued), scales [4096] f32
//   out [32,14336] f32
//
// R8: int8 IMMA path (R7) with the swizzle carry bug fixed: second-half W
// store must be SWZ(base)^16, not SWZ(base)+16 (bit4 of SWZ(base) = row&1,
// arithmetic +16 carried into bit5 for odd rows and corrupted the tile).
// W bytes packed via PRMT; activations quantized per-token to q1*128+q2
// (14-bit, exact s32 accumulation); out = d_t*(128*acc1 + acc2).
// Split-K x2, TILE_M=64, KC=128, double buffer, 1 barrier/chunk, 3 CTAs/SM.
// ---------------------------------------------------------------------------

#define SWZ(off) ((off) ^ (((off) >> 3) & 0x70))

static constexpr int TOKENS = 32;
static constexpr int INF    = 4096;
static constexpr int OUTF   = 14336;
static constexpr int TILE_M = 64;
static constexpr int KSPLIT = 2;
static constexpr int KHALF  = INF / KSPLIT;     // 2048
static constexpr int KC     = 128;              // K elements per chunk
static constexpr int NITER  = KHALF / KC;       // 16

// per-buffer SMEM layout (bytes): rows of 128 int8, SW128 swizzle
static constexpr int W_OFF   = 0;                   // 64 x 128 int8 = 8 KB
static constexpr int Q1_OFF  = TILE_M * 128;        // 8192; 32 x 128 int8 = 4 KB
static constexpr int Q2_OFF  = Q1_OFF + TOKENS * 128;   // 12288
static constexpr int BUF_BYTES  = Q2_OFF + TOKENS * 128; // 16384
static constexpr int SMEM_TOTAL = 2 * BUF_BYTES;         // 32768

// quantized activations + per-token scale (built by prep kernel)
__device__ int8_t g_q1[TOKENS * INF];
__device__ int8_t g_q2[TOKENS * INF];
__device__ float  g_d[TOKENS];

// ---------------- helpers ----------------
__device__ __forceinline__ uint32_t smem_u32(const void* p) {
    uint32_t a;
    asm("{ .reg .u64 t; cvta.to.shared.u64 t, %1; cvt.u32.u64 %0, t; }"
        : "=r"(a) : "l"(p));
    return a;
}

__device__ __forceinline__ void sts128(uint32_t addr, uint32_t r0, uint32_t r1,
                                       uint32_t r2, uint32_t r3) {
    asm volatile("st.shared.v4.b32 [%0], {%1, %2, %3, %4};"
                 :: "r"(addr), "r"(r0), "r"(r1), "r"(r2), "r"(r3) : "memory");
}

__device__ __forceinline__ void cp16(uint32_t dst, const void* src) {
    asm volatile("cp.async.cg.shared.global [%0], [%1], 16;"
                 :: "r"(dst), "l"(src) : "memory");
}
__device__ __forceinline__ void cp_commit() {
    asm volatile("cp.async.commit_group;" ::: "memory");
}
__device__ __forceinline__ void cp_wait0() {
    asm volatile("cp.async.wait_group 0;" ::: "memory");
}

// pack low bytes of 4 int32 -> 1 u32  (3x PRMT)
__device__ __forceinline__ uint32_t pack4(int a0, int a1, int a2, int a3) {
    uint32_t p01 = __byte_perm((uint32_t)a0, (uint32_t)a1, 0x0040);
    uint32_t p23 = __byte_perm((uint32_t)a2, (uint32_t)a3, 0x0040);
    return __byte_perm(p01, p23, 0x5410);
}

__device__ __forceinline__ void ldsm_x4(uint32_t addr, uint32_t& r0, uint32_t& r1,
                                        uint32_t& r2, uint32_t& r3) {
    asm volatile("ldmatrix.sync.aligned.m8n8.x4.shared.b16 {%0,%1,%2,%3}, [%4];"
                 : "=r"(r0), "=r"(r1), "=r"(r2), "=r"(r3) : "r"(addr));
}

__device__ __forceinline__ void mma_s8(int* d, const uint32_t* a, const uint32_t* b) {
    asm volatile(
        "mma.sync.aligned.m16n8k32.row.col.s32.s8.s8.s32 "
        "{%0,%1,%2,%3}, {%4,%5,%6,%7}, {%8,%9}, {%0,%1,%2,%3};"
        : "+r"(d[0]), "+r"(d[1]), "+r"(d[2]), "+r"(d[3])
        : "r"(a[0]), "r"(a[1]), "r"(a[2]), "r"(a[3]), "r"(b[0]), "r"(b[1]));
}

// ---------------- prep: per-token quantize + zero the output ----------------
static constexpr int OUT_ELEMS = TOKENS * OUTF;        // 458752
static constexpr int OUT_VEC4  = OUT_ELEMS / 4;        // 114688

__global__ void __launch_bounds__(256)
prep_kernel(const float* __restrict__ x, const float* __restrict__ s,
            float4* __restrict__ out4) {
    const int t   = blockIdx.x;     // token
    const int tid = threadIdx.x;
    const int base = tid * 16;

    // load 16 elems, scale, local max
    float xs[16];
    float m = 0.0f;
#pragma unroll
    for (int j = 0; j < 16; j += 4) {
        float4 xv = *(const float4*)(x + t * INF + base + j);
        float4 sv = *(const float4*)(s + base + j);
        xs[j]     = xv.x * sv.x;
        xs[j + 1] = xv.y * sv.y;
        xs[j + 2] = xv.z * sv.z;
        xs[j + 3] = xv.w * sv.w;
        m = fmaxf(m, fmaxf(fmaxf(fabsf(xs[j]), fabsf(xs[j + 1])),
                           fmaxf(fabsf(xs[j + 2]), fabsf(xs[j + 3]))));
    }
    // block max reduce
#pragma unroll
    for (int o = 16; o > 0; o >>= 1)
        m = fmaxf(m, __shfl_xor_sync(0xffffffffu, m, o));
    __shared__ float red[8];
    if ((tid & 31) == 0) red[tid >> 5] = m;
    __syncthreads();
    float mall = red[0];
#pragma unroll
    for (int j = 1; j < 8; j++) mall = fmaxf(mall, red[j]);

    const float d  = fmaxf(mall, 1e-30f) * (1.0f / 16256.0f);
    const float rd = 1.0f / d;

    uint32_t p1[4], p2[4];
#pragma unroll
    for (int j = 0; j < 16; j += 4) {
        int q1[4], q2[4];
#pragma unroll
        for (int u = 0; u < 4; u++) {
            float z = xs[j + u] * rd;
            int a = __float2int_rn(z * 0.0078125f);        // z/128
            int b = __float2int_rn(z - 128.0f * (float)a); // residual
            q1[u] = a;
            q2[u] = b;
        }
        p1[j >> 2] = pack4(q1[0], q1[1], q1[2], q1[3]);
        p2[j >> 2] = pack4(q2[0], q2[1], q2[2], q2[3]);
    }
    *(uint4*)(g_q1 + t * INF + base) = make_uint4(p1[0], p1[1], p1[2], p1[3]);
    *(uint4*)(g_q2 + t * INF + base) = make_uint4(p2[0], p2[1], p2[2], p2[3]);
    if (tid == 0) g_d[t] = d;

    // zero output (grid-stride over 32 blocks)
    for (int i = blockIdx.x * 256 + tid; i < OUT_VEC4; i += 32 * 256)
        out4[i] = make_float4(0.f, 0.f, 0.f, 0.f);
}

// ---------------- main GEMM ----------------
__global__ void __launch_bounds__(256, 3)
qgemm_kernel(const int* __restrict__ W, float* __restrict__ out) {
    __shared__ __align__(1024) char smem[SMEM_TOTAL];
    const uint32_t sb = smem_u32(smem);
    const int tid = threadIdx.x;
    const int lane = tid & 31;
    const int wid = tid >> 5;
    const int rg = wid >> 1;     // row group 0..3 (16 rows each)
    const int th = wid & 1;      // token half 0..1 (16 tokens each)

    const int tile = blockIdx.x >> 1;
    const int kbase = (blockIdx.x & 1) * KHALF;
    const int row_base = tile * TILE_M;

    // ---- W producer: thread -> (row, 128B k-segment) ----
    const int wrow = tid >> 2;           // 0..63
    const int wseg = tid & 3;            // 0..3 (x 32 ints = 32 int8 out bytes)
    const int4* wp = (const int4*)(W + (size_t)(row_base + wrow) * INF + kbase + wseg * 32);
    const uint32_t wstsA = SWZ(wrow * 128 + wseg * 32);
    const uint32_t wstsB = wstsA ^ 16;   // == SWZ(base + 16): XOR, NOT add (bit4 carry bug)

    // ---- q producer: thread -> (token, 16B granule) ----
    const int qrow = tid >> 3;           // 0..31
    const int qcol = tid & 7;            // 0..7
    const char* q1p = (const char*)(g_q1 + qrow * INF + kbase + qcol * 16);
    const char* q2p = (const char*)(g_q2 + qrow * INF + kbase + qcol * 16);
    const uint32_t qsts = SWZ(qrow * 128 + qcol * 16);

    // ---- ldmatrix lane geometry (byte-identical to the bf16 k16 mapping) ----
    const int rowA  = rg * 16 + (lane & 15);
    const int aCsel = (lane & 16);              // +16B (k+16 int8)
    const int tokB  = th * 16 + (lane & 7) + ((lane & 16) >> 1);
    const int bCsel = (lane & 8) * 2;           // +16B for k+16 tile

    int acc1[2][4], acc2[2][4];
#pragma unroll
    for (int n = 0; n < 2; n++)
#pragma unroll
        for (int r = 0; r < 4; r++) { acc1[n][r] = 0; acc2[n][r] = 0; }

    int4 wst[8];   // staged W chunk (constant-indexed only)

    // ---- prologue: W chunk 0 -> regs; q chunk 0 -> cp.async ----
#pragma unroll
    for (int j = 0; j < 8; j++) wst[j] = wp[j];
    wp += 32;   // +128 ints

    cp16(sb + Q1_OFF + qsts, q1p); q1p += KC;
    cp16(sb + Q2_OFF + qsts, q2p); q2p += KC;
    cp_commit();

#pragma unroll 1
    for (int it = 0; it < NITER; ++it) {
        const uint32_t bufb = sb + (it & 1) * BUF_BYTES;

        // ---- pack staged W -> int8 tile (readers proven done via sync(it-1)) ----
        {
            uint32_t p0 = pack4(wst[0].x, wst[0].y, wst[0].z, wst[0].w);
            uint32_t p1 = pack4(wst[1].x, wst[1].y, wst[1].z, wst[1].w);
            uint32_t p2 = pack4(wst[2].x, wst[2].y, wst[2].z, wst[2].w);
            uint32_t p3 = pack4(wst[3].x, wst[3].y, wst[3].z, wst[3].w);
            sts128(bufb + W_OFF + wstsA, p0, p1, p2, p3);
            p0 = pack4(wst[4].x, wst[4].y, wst[4].z, wst[4].w);
            p1 = pack4(wst[5].x, wst[5].y, wst[5].z, wst[5].w);
            p2 = pack4(wst[6].x, wst[6].y, wst[6].z, wst[6].w);
            p3 = pack4(wst[7].x, wst[7].y, wst[7].z, wst[7].w);
            sts128(bufb + W_OFF + wstsB, p0, p1, p2, p3);
        }

        // ---- LDG W chunk it+1 (consumed next iteration top) ----
        if (it + 1 < NITER) {
#pragma unroll
            for (int j = 0; j < 8; j++) wst[j] = wp[j];
            wp += 32;
        }

        cp_wait0();        // q(it) landed
        __syncthreads();   // tile (it) visible; compute(it-1) done on all warps

        // ---- q(it+1) cp.async into the other buffer ----
        if (it + 1 < NITER) {
            const uint32_t nb = sb + ((it + 1) & 1) * BUF_BYTES;
            cp16(nb + Q1_OFF + qsts, q1p); q1p += KC;
            cp16(nb + Q2_OFF + qsts, q2p); q2p += KC;
            cp_commit();
        }

        // ---- compute: 4 k32-steps x 2 n-groups x (q1,q2) ----
#pragma unroll
        for (int ks = 0; ks < 4; ks++) {
            uint32_t a[4], b[4];
            const int kb = ks * 32;
            ldsm_x4(bufb + W_OFF + SWZ(rowA * 128 + kb + aCsel), a[0], a[1], a[2], a[3]);
            const int bb = tokB * 128 + kb + bCsel;
            ldsm_x4(bufb + Q1_OFF + SWZ(bb), b[0], b[1], b[2], b[3]);
            mma_s8(acc1[0], a, b + 0);
            mma_s8(acc1[1], a, b + 2);
            ldsm_x4(bufb + Q2_OFF + SWZ(bb), b[0], b[1], b[2], b[3]);
            mma_s8(acc2[0], a, b + 0);
            mma_s8(acc2[1], a, b + 2);
        }
    }

    // ---- epilogue: dequant + atomicAdd (2 deterministic contributors) ----
    const int g = lane >> 2;
    const int t2 = (lane & 3) * 2;
    const int f0 = row_base + rg * 16 + g;
#pragma unroll
    for (int nt = 0; nt < 2; nt++) {
        const int tok = th * 16 + nt * 8 + t2;
        const float d0 = g_d[tok];
        const float d1 = g_d[tok + 1];
        float v0 = d0 * (128.0f * (float)acc1[nt][0] + (float)acc2[nt][0]);
        float v1 = d1 * (128.0f * (float)acc1[nt][1] + (float)acc2[nt][1]);
        float v2 = d0 * (128.0f * (float)acc1[nt][2] + (float)acc2[nt][2]);
        float v3 = d1 * (128.0f * (float)acc1[nt][3] + (float)acc2[nt][3]);
        atomicAdd(&out[(size_t)tok * OUTF + f0],           v0);
        atomicAdd(&out[(size_t)(tok + 1) * OUTF + f0],     v1);
        atomicAdd(&out[(size_t)tok * OUTF + f0 + 8],       v2);
        atomicAdd(&out[(size_t)(tok + 1) * OUTF + f0 + 8], v3);
    }
}

// ---------------- launch ----------------
extern "C" void kernel_launch(void* const* d_in, const int* in_sizes, int n_in,
                              void* d_out, int out_size) {
    const float* x      = (const float*)d_in[0];
    const int*   weight = (const int*)d_in[1];
    const float* scales = (const float*)d_in[2];
    float*       out    = (float*)d_out;
    (void)in_sizes; (void)n_in; (void)out_size;

    prep_kernel<<<TOKENS, 256>>>(x, scales, (float4*)out);
    qgemm_kernel<<<(OUTF / TILE_M) * KSPLIT, 256>>>(weight, out);
}

// round 9
// speedup vs baseline: 1.6499x; 1.6499x over previous
#include <cuda_runtime.h>
#include <cuda_fp16.h>
#include <cstdint>

// ---------------------------------------------------------------------------
// out[t,o] = sum_i (x[t,i]*scales[i]) * W[o,i]
//   x [32,4096] f32, W [14336,4096] int32 (int8-valued), scales [4096] f32
//   out [32,14336] f32
//
// R9: fp16 HMMA (m16n8k16.f16, fp32 accum), SINGLE fp16 activation (no hi/lo
// split): W<=127 exact in fp16, xs fp16 rounding -> rel_err ~2.5e-4 < 1e-3.
// Halves B-side L1/tensor work vs R6 (L1 was 79.6%, co-binding with DRAM).
// R8 showed legacy int8 IMMA is a slow path on sm_103 (tensor=65%) — avoided.
// Split-K x2, TILE_M=64, KC=64, depth-2 W reg prefetch (named arrays),
// double buffer, 1 barrier/chunk, 3 CTAs/SM, fused zero+prep.
// ---------------------------------------------------------------------------

#define SWZ(off) ((off) ^ (((off) >> 3) & 0x70))

static constexpr int TOKENS = 32;
static constexpr int INF    = 4096;
static constexpr int OUTF   = 14336;
static constexpr int TILE_M = 64;
static constexpr int KSPLIT = 2;
static constexpr int KHALF  = INF / KSPLIT;     // 2048
static constexpr int KC     = 64;               // K elements per chunk
static constexpr int NITER  = KHALF / KC;       // 32 (even)
static constexpr int NPAIR  = NITER / 2;        // 16

// per-buffer SMEM layout (bytes)
static constexpr int A_BYTES = TILE_M * 128;        // 8192 (64 rows x 128B, SW128)
static constexpr int X_OFF   = A_BYTES;             // xs tile 32 x 64 fp16 = 4096
static constexpr int BUF_BYTES  = A_BYTES + TOKENS * 128;  // 12288
static constexpr int SMEM_TOTAL = 2 * BUF_BYTES;           // 24576

// fp16 scaled activations (built by prep kernel)
__device__ __half g_xs[TOKENS * INF];

// ---------------- helpers ----------------
__device__ __forceinline__ uint32_t smem_u32(const void* p) {
    uint32_t a;
    asm("{ .reg .u64 t; cvta.to.shared.u64 t, %1; cvt.u32.u64 %0, t; }"
        : "=r"(a) : "l"(p));
    return a;
}

__device__ __forceinline__ void sts128(uint32_t addr, uint32_t r0, uint32_t r1,
                                       uint32_t r2, uint32_t r3) {
    asm volatile("st.shared.v4.b32 [%0], {%1, %2, %3, %4};"
                 :: "r"(addr), "r"(r0), "r"(r1), "r"(r2), "r"(r3) : "memory");
}

__device__ __forceinline__ void cp16(uint32_t dst, const void* src) {
    asm volatile("cp.async.cg.shared.global [%0], [%1], 16;"
                 :: "r"(dst), "l"(src) : "memory");
}
__device__ __forceinline__ void cp_commit() {
    asm volatile("cp.async.commit_group;" ::: "memory");
}
__device__ __forceinline__ void cp_wait0() {
    asm volatile("cp.async.wait_group 0;" ::: "memory");
}

// pack two ints (|v|<=127, exact in fp16) -> half2 bits
__device__ __forceinline__ uint32_t packhf(int a, int b) {
    __half2 h = __floats2half2_rn((float)a, (float)b);
    return *reinterpret_cast<uint32_t*>(&h);
}

__device__ __forceinline__ void ldsm_x4(uint32_t addr, uint32_t& r0, uint32_t& r1,
                                        uint32_t& r2, uint32_t& r3) {
    asm volatile("ldmatrix.sync.aligned.m8n8.x4.shared.b16 {%0,%1,%2,%3}, [%4];"
                 : "=r"(r0), "=r"(r1), "=r"(r2), "=r"(r3) : "r"(addr));
}

__device__ __forceinline__ void mma_16816(float* d, const uint32_t* a, const uint32_t* b) {
    asm volatile(
        "mma.sync.aligned.m16n8k16.row.col.f32.f16.f16.f32 "
        "{%0,%1,%2,%3}, {%4,%5,%6,%7}, {%8,%9}, {%0,%1,%2,%3};"
        : "+f"(d[0]), "+f"(d[1]), "+f"(d[2]), "+f"(d[3])
        : "r"(a[0]), "r"(a[1]), "r"(a[2]), "r"(a[3]), "r"(b[0]), "r"(b[1]));
}

// ---------------- prep: xs = fp16(x*scales) + zero the output ----------------
static constexpr int OUT_ELEMS = TOKENS * OUTF;        // 458752
static constexpr int OUT_VEC4  = OUT_ELEMS / 4;        // 114688

__global__ void prep_kernel(const float* __restrict__ x, const float* __restrict__ s,
                            float4* __restrict__ out4) {
    int i = blockIdx.x * blockDim.x + threadIdx.x;
    if (i < TOKENS * INF) {
        int k = i & (INF - 1);
        g_xs[i] = __float2half_rn(x[i] * s[k]);
    }
    if (i < OUT_VEC4) {
        out4[i] = make_float4(0.f, 0.f, 0.f, 0.f);
    }
}

// ---------------- main GEMM ----------------
__global__ void __launch_bounds__(256, 3)
qgemm_kernel(const int* __restrict__ W, float* __restrict__ out) {
    __shared__ __align__(1024) char smem[SMEM_TOTAL];
    const uint32_t sb = smem_u32(smem);
    const int tid = threadIdx.x;
    const int lane = tid & 31;
    const int wid = tid >> 5;
    const int rg = wid >> 1;     // row group 0..3 (16 rows each)
    const int th = wid & 1;      // token half 0..1 (16 tokens each)

    const int tile = blockIdx.x >> 1;
    const int kbase = (blockIdx.x & 1) * KHALF;
    const int row_base = tile * TILE_M;

    // ---- W producer coordinates: 2 granules of 8 int32 per thread ----
    const int4* wp0;
    const int4* wp1;
    uint32_t wsts0, wsts1;
    {
        int g0 = tid;            // granule 0..255
        int g1 = tid + 256;      // granule 256..511
        int m0 = g0 >> 3, c0 = g0 & 7;
        int m1 = g1 >> 3, c1 = g1 & 7;
        wp0 = (const int4*)(W + (size_t)(row_base + m0) * INF + kbase + c0 * 8);
        wp1 = (const int4*)(W + (size_t)(row_base + m1) * INF + kbase + c1 * 8);
        wsts0 = SWZ(m0 * 128 + c0 * 16);
        wsts1 = SWZ(m1 * 128 + c1 * 16);
    }
    // ---- xs producer: 1 granule of 8 fp16 per thread ----
    const char* xp;
    uint32_t xsts;
    {
        int t0 = tid >> 3, c0 = tid & 7;
        xp = (const char*)(g_xs + t0 * INF + kbase + c0 * 8);
        xsts = X_OFF + SWZ(t0 * 128 + c0 * 16);
    }

    // ---- ldmatrix lane geometry ----
    const int rowA  = rg * 16 + (lane & 7) + (lane & 8);
    const int aCsel = (lane & 16);              // +8 fp16 cols -> +16 bytes
    const int tokB  = th * 16 + (lane & 7) + ((lane & 16) >> 1);
    const int bCsel = (lane & 8) * 2;           // +16 bytes for k+8 tile

    float acc[2][4];
#pragma unroll
    for (int n = 0; n < 2; n++)
#pragma unroll
        for (int r = 0; r < 4; r++) acc[n][r] = 0.0f;

    // depth-2 W staging: NAMED arrays, constant indices only
    int4 w0[4], w1[4];

    // ---- prologue: W chunks 0,1 -> regs; xs chunk 0 -> cp.async ----
    w0[0] = wp0[0]; w0[1] = wp0[1];
    w0[2] = wp1[0]; w0[3] = wp1[1];
    wp0 += 16; wp1 += 16;                      // +KC ints
    w1[0] = wp0[0]; w1[1] = wp0[1];
    w1[2] = wp1[0]; w1[3] = wp1[1];
    wp0 += 16; wp1 += 16;

    cp16(sb + xsts, xp); xp += KC * 2;
    cp_commit();

    const uint32_t buf0 = sb;
    const uint32_t buf1 = sb + BUF_BYTES;

#pragma unroll 1
    for (int itp = 0; itp < NPAIR; ++itp) {
        // ================= even chunk e = 2*itp, buffer 0 =================
        {
            uint32_t r0 = packhf(w0[0].x, w0[0].y), r1 = packhf(w0[0].z, w0[0].w);
            uint32_t r2 = packhf(w0[1].x, w0[1].y), r3 = packhf(w0[1].z, w0[1].w);
            sts128(buf0 + wsts0, r0, r1, r2, r3);
            r0 = packhf(w0[2].x, w0[2].y); r1 = packhf(w0[2].z, w0[2].w);
            r2 = packhf(w0[3].x, w0[3].y); r3 = packhf(w0[3].z, w0[3].w);
            sts128(buf0 + wsts1, r0, r1, r2, r3);

            // refill w0 from chunk e+2
            if (itp + 1 < NPAIR) {
                w0[0] = wp0[0]; w0[1] = wp0[1];
                w0[2] = wp1[0]; w0[3] = wp1[1];
                wp0 += 16; wp1 += 16;
            }

            cp_wait0();        // xs(e) landed in buf0
            __syncthreads();   // buf0 tile visible; prior buf1 readers done

            // xs(e+1) -> buf1
            cp16(buf1 + xsts, xp); xp += KC * 2;
            cp_commit();

            // compute buf0
#pragma unroll
            for (int ks = 0; ks < 4; ks++) {
                uint32_t a[4], b[4];
                const int kb = ks * 32;
                ldsm_x4(buf0 + SWZ(rowA * 128 + kb + aCsel), a[0], a[1], a[2], a[3]);
                ldsm_x4(buf0 + X_OFF + SWZ(tokB * 128 + kb + bCsel),
                        b[0], b[1], b[2], b[3]);
                mma_16816(acc[0], a, b + 0);
                mma_16816(acc[1], a, b + 2);
            }
        }
        // ================= odd chunk o = e+1, buffer 1 =================
        {
            uint32_t r0 = packhf(w1[0].x, w1[0].y), r1 = packhf(w1[0].z, w1[0].w);
            uint32_t r2 = packhf(w1[1].x, w1[1].y), r3 = packhf(w1[1].z, w1[1].w);
            sts128(buf1 + wsts0, r0, r1, r2, r3);
            r0 = packhf(w1[2].x, w1[2].y); r1 = packhf(w1[2].z, w1[2].w);
            r2 = packhf(w1[3].x, w1[3].y); r3 = packhf(w1[3].z, w1[3].w);
            sts128(buf1 + wsts1, r0, r1, r2, r3);

            // refill w1 from chunk o+2
            if (itp + 1 < NPAIR) {
                w1[0] = wp0[0]; w1[1] = wp0[1];
                w1[2] = wp1[0]; w1[3] = wp1[1];
                wp0 += 16; wp1 += 16;
            }

            cp_wait0();        // xs(o) landed in buf1
            __syncthreads();   // buf1 tile visible; buf0 readers done

            // xs(o+1) -> buf0
            if (itp + 1 < NPAIR) {
                cp16(buf0 + xsts, xp); xp += KC * 2;
                cp_commit();
            }

            // compute buf1
#pragma unroll
            for (int ks = 0; ks < 4; ks++) {
                uint32_t a[4], b[4];
                const int kb = ks * 32;
                ldsm_x4(buf1 + SWZ(rowA * 128 + kb + aCsel), a[0], a[1], a[2], a[3]);
                ldsm_x4(buf1 + X_OFF + SWZ(tokB * 128 + kb + bCsel),
                        b[0], b[1], b[2], b[3]);
                mma_16816(acc[0], a, b + 0);
                mma_16816(acc[1], a, b + 2);
            }
        }
    }

    // ---- epilogue: atomicAdd partials (2 deterministic contributors/elem) ----
    const int g = lane >> 2;
    const int t2 = (lane & 3) * 2;
    const int f0 = row_base + rg * 16 + g;
#pragma unroll
    for (int nt = 0; nt < 2; nt++) {
        const int tok = th * 16 + nt * 8 + t2;
        atomicAdd(&out[(size_t)tok * OUTF + f0],           acc[nt][0]);
        atomicAdd(&out[(size_t)(tok + 1) * OUTF + f0],     acc[nt][1]);
        atomicAdd(&out[(size_t)tok * OUTF + f0 + 8],       acc[nt][2]);
        atomicAdd(&out[(size_t)(tok + 1) * OUTF + f0 + 8], acc[nt][3]);
    }
}

// ---------------- launch ----------------
extern "C" void kernel_launch(void* const* d_in, const int* in_sizes, int n_in,
                              void* d_out, int out_size) {
    const float* x      = (const float*)d_in[0];
    const int*   weight = (const int*)d_in[1];
    const float* scales = (const float*)d_in[2];
    float*       out    = (float*)d_out;
    (void)in_sizes; (void)n_in; (void)out_size;

    prep_kernel<<<(TOKENS * INF + 255) / 256, 256>>>(x, scales, (float4*)out);
    qgemm_kernel<<<(OUTF / TILE_M) * KSPLIT, 256>>>(weight, out);
}

// round 10
// speedup vs baseline: 1.7252x; 1.0457x over previous
#include <cuda_runtime.h>
#include <cuda_fp16.h>
#include <cstdint>

// ---------------------------------------------------------------------------
// out[t,o] = sum_i (x[t,i]*scales[i]) * W[o,i]
//   x [32,4096] f32, W [14336,4096] int32 (int8-valued), scales [4096] f32
//   out [32,14336] f32
//
// R10: R9 (fp16 HMMA, single fp16 activation, depth-2 W reg prefetch) with a
// smaller sync domain: TILE_M=32, 128-thread CTAs (4 warps), 896 CTAs,
// 6 CTAs/SM. Halves the per-barrier convoy and doubles independent pipeline
// units per SM (R9 showed occ pinned at 3-CTA cap, issue=18%, DRAM stuck 67%).
// ---------------------------------------------------------------------------

#define SWZ(off) ((off) ^ (((off) >> 3) & 0x70))

static constexpr int TOKENS = 32;
static constexpr int INF    = 4096;
static constexpr int OUTF   = 14336;
static constexpr int TILE_M = 32;
static constexpr int NTHR   = 128;
static constexpr int KSPLIT = 2;
static constexpr int KHALF  = INF / KSPLIT;     // 2048
static constexpr int KC     = 64;               // K elements per chunk
static constexpr int NITER  = KHALF / KC;       // 32 (even)
static constexpr int NPAIR  = NITER / 2;        // 16

// per-buffer SMEM layout (bytes)
static constexpr int A_BYTES = TILE_M * 128;        // 4096 (32 rows x 128B, SW128)
static constexpr int X_OFF   = A_BYTES;             // xs tile 32 x 64 fp16 = 4096
static constexpr int BUF_BYTES  = A_BYTES + TOKENS * 128;  // 8192
static constexpr int SMEM_TOTAL = 2 * BUF_BYTES;           // 16384

// fp16 scaled activations (built by prep kernel)
__device__ __half g_xs[TOKENS * INF];

// ---------------- helpers ----------------
__device__ __forceinline__ uint32_t smem_u32(const void* p) {
    uint32_t a;
    asm("{ .reg .u64 t; cvta.to.shared.u64 t, %1; cvt.u32.u64 %0, t; }"
        : "=r"(a) : "l"(p));
    return a;
}

__device__ __forceinline__ void sts128(uint32_t addr, uint32_t r0, uint32_t r1,
                                       uint32_t r2, uint32_t r3) {
    asm volatile("st.shared.v4.b32 [%0], {%1, %2, %3, %4};"
                 :: "r"(addr), "r"(r0), "r"(r1), "r"(r2), "r"(r3) : "memory");
}

__device__ __forceinline__ void cp16(uint32_t dst, const void* src) {
    asm volatile("cp.async.cg.shared.global [%0], [%1], 16;"
                 :: "r"(dst), "l"(src) : "memory");
}
__device__ __forceinline__ void cp_commit() {
    asm volatile("cp.async.commit_group;" ::: "memory");
}
__device__ __forceinline__ void cp_wait0() {
    asm volatile("cp.async.wait_group 0;" ::: "memory");
}

// pack two ints (|v|<=127, exact in fp16) -> half2 bits
__device__ __forceinline__ uint32_t packhf(int a, int b) {
    __half2 h = __floats2half2_rn((float)a, (float)b);
    return *reinterpret_cast<uint32_t*>(&h);
}

__device__ __forceinline__ void ldsm_x4(uint32_t addr, uint32_t& r0, uint32_t& r1,
                                        uint32_t& r2, uint32_t& r3) {
    asm volatile("ldmatrix.sync.aligned.m8n8.x4.shared.b16 {%0,%1,%2,%3}, [%4];"
                 : "=r"(r0), "=r"(r1), "=r"(r2), "=r"(r3) : "r"(addr));
}

__device__ __forceinline__ void mma_16816(float* d, const uint32_t* a, const uint32_t* b) {
    asm volatile(
        "mma.sync.aligned.m16n8k16.row.col.f32.f16.f16.f32 "
        "{%0,%1,%2,%3}, {%4,%5,%6,%7}, {%8,%9}, {%0,%1,%2,%3};"
        : "+f"(d[0]), "+f"(d[1]), "+f"(d[2]), "+f"(d[3])
        : "r"(a[0]), "r"(a[1]), "r"(a[2]), "r"(a[3]), "r"(b[0]), "r"(b[1]));
}

// ---------------- prep: xs = fp16(x*scales) + zero the output ----------------
static constexpr int OUT_ELEMS = TOKENS * OUTF;        // 458752
static constexpr int OUT_VEC4  = OUT_ELEMS / 4;        // 114688

__global__ void prep_kernel(const float* __restrict__ x, const float* __restrict__ s,
                            float4* __restrict__ out4) {
    int i = blockIdx.x * blockDim.x + threadIdx.x;
    if (i < TOKENS * INF) {
        int k = i & (INF - 1);
        g_xs[i] = __float2half_rn(x[i] * s[k]);
    }
    if (i < OUT_VEC4) {
        out4[i] = make_float4(0.f, 0.f, 0.f, 0.f);
    }
}

// ---------------- main GEMM ----------------
__global__ void __launch_bounds__(NTHR, 6)
qgemm_kernel(const int* __restrict__ W, float* __restrict__ out) {
    __shared__ __align__(1024) char smem[SMEM_TOTAL];
    const uint32_t sb = smem_u32(smem);
    const int tid = threadIdx.x;
    const int lane = tid & 31;
    const int wid = tid >> 5;      // 0..3
    const int rg = wid >> 1;       // row group 0..1 (16 rows each)
    const int th = wid & 1;        // token half 0..1 (16 tokens each)

    const int tile = blockIdx.x >> 1;
    const int kbase = (blockIdx.x & 1) * KHALF;
    const int row_base = tile * TILE_M;

    // ---- W producer coordinates: 2 granules of 8 int32 per thread ----
    // 32 rows x 8 granules = 256 granules, 2 per thread
    const int4* wp0;
    const int4* wp1;
    uint32_t wsts0, wsts1;
    {
        int g0 = tid;            // granule 0..127
        int g1 = tid + NTHR;     // granule 128..255
        int m0 = g0 >> 3, c0 = g0 & 7;
        int m1 = g1 >> 3, c1 = g1 & 7;
        wp0 = (const int4*)(W + (size_t)(row_base + m0) * INF + kbase + c0 * 8);
        wp1 = (const int4*)(W + (size_t)(row_base + m1) * INF + kbase + c1 * 8);
        wsts0 = SWZ(m0 * 128 + c0 * 16);
        wsts1 = SWZ(m1 * 128 + c1 * 16);
    }
    // ---- xs producer: 2 granules of 8 fp16 per thread (32 tok x 8 gran) ----
    const char* xpA;
    const char* xpB;
    uint32_t xstsA, xstsB;
    {
        int i0 = tid;            // 0..127
        int i1 = tid + NTHR;     // 128..255
        int t0 = i0 >> 3, c0 = i0 & 7;
        int t1 = i1 >> 3, c1 = i1 & 7;
        xpA = (const char*)(g_xs + t0 * INF + kbase + c0 * 8);
        xpB = (const char*)(g_xs + t1 * INF + kbase + c1 * 8);
        xstsA = X_OFF + SWZ(t0 * 128 + c0 * 16);
        xstsB = X_OFF + SWZ(t1 * 128 + c1 * 16);
    }

    // ---- ldmatrix lane geometry ----
    const int rowA  = rg * 16 + (lane & 7) + (lane & 8);
    const int aCsel = (lane & 16);              // +8 fp16 cols -> +16 bytes
    const int tokB  = th * 16 + (lane & 7) + ((lane & 16) >> 1);
    const int bCsel = (lane & 8) * 2;           // +16 bytes for k+8 tile

    float acc[2][4];
#pragma unroll
    for (int n = 0; n < 2; n++)
#pragma unroll
        for (int r = 0; r < 4; r++) acc[n][r] = 0.0f;

    // depth-2 W staging: NAMED arrays, constant indices only
    int4 w0[4], w1[4];

    // ---- prologue: W chunks 0,1 -> regs; xs chunk 0 -> cp.async ----
    w0[0] = wp0[0]; w0[1] = wp0[1];
    w0[2] = wp1[0]; w0[3] = wp1[1];
    wp0 += 16; wp1 += 16;                      // +KC ints
    w1[0] = wp0[0]; w1[1] = wp0[1];
    w1[2] = wp1[0]; w1[3] = wp1[1];
    wp0 += 16; wp1 += 16;

    cp16(sb + xstsA, xpA); xpA += KC * 2;
    cp16(sb + xstsB, xpB); xpB += KC * 2;
    cp_commit();

    const uint32_t buf0 = sb;
    const uint32_t buf1 = sb + BUF_BYTES;

#pragma unroll 1
    for (int itp = 0; itp < NPAIR; ++itp) {
        // ================= even chunk e = 2*itp, buffer 0 =================
        {
            uint32_t r0 = packhf(w0[0].x, w0[0].y), r1 = packhf(w0[0].z, w0[0].w);
            uint32_t r2 = packhf(w0[1].x, w0[1].y), r3 = packhf(w0[1].z, w0[1].w);
            sts128(buf0 + wsts0, r0, r1, r2, r3);
            r0 = packhf(w0[2].x, w0[2].y); r1 = packhf(w0[2].z, w0[2].w);
            r2 = packhf(w0[3].x, w0[3].y); r3 = packhf(w0[3].z, w0[3].w);
            sts128(buf0 + wsts1, r0, r1, r2, r3);

            // refill w0 from chunk e+2
            if (itp + 1 < NPAIR) {
                w0[0] = wp0[0]; w0[1] = wp0[1];
                w0[2] = wp1[0]; w0[3] = wp1[1];
                wp0 += 16; wp1 += 16;
            }

            cp_wait0();        // xs(e) landed in buf0
            __syncthreads();   // buf0 tile visible; prior buf1 readers done

            // xs(e+1) -> buf1
            cp16(buf1 + xstsA, xpA); xpA += KC * 2;
            cp16(buf1 + xstsB, xpB); xpB += KC * 2;
            cp_commit();

            // compute buf0
#pragma unroll
            for (int ks = 0; ks < 4; ks++) {
                uint32_t a[4], b[4];
                const int kb = ks * 32;
                ldsm_x4(buf0 + SWZ(rowA * 128 + kb + aCsel), a[0], a[1], a[2], a[3]);
                ldsm_x4(buf0 + X_OFF + SWZ(tokB * 128 + kb + bCsel),
                        b[0], b[1], b[2], b[3]);
                mma_16816(acc[0], a, b + 0);
                mma_16816(acc[1], a, b + 2);
            }
        }
        // ================= odd chunk o = e+1, buffer 1 =================
        {
            uint32_t r0 = packhf(w1[0].x, w1[0].y), r1 = packhf(w1[0].z, w1[0].w);
            uint32_t r2 = packhf(w1[1].x, w1[1].y), r3 = packhf(w1[1].z, w1[1].w);
            sts128(buf1 + wsts0, r0, r1, r2, r3);
            r0 = packhf(w1[2].x, w1[2].y); r1 = packhf(w1[2].z, w1[2].w);
            r2 = packhf(w1[3].x, w1[3].y); r3 = packhf(w1[3].z, w1[3].w);
            sts128(buf1 + wsts1, r0, r1, r2, r3);

            // refill w1 from chunk o+2
            if (itp + 1 < NPAIR) {
                w1[0] = wp0[0]; w1[1] = wp0[1];
                w1[2] = wp1[0]; w1[3] = wp1[1];
                wp0 += 16; wp1 += 16;
            }

            cp_wait0();        // xs(o) landed in buf1
            __syncthreads();   // buf1 tile visible; buf0 readers done

            // xs(o+1) -> buf0
            if (itp + 1 < NPAIR) {
                cp16(buf0 + xstsA, xpA); xpA += KC * 2;
                cp16(buf0 + xstsB, xpB); xpB += KC * 2;
                cp_commit();
            }

            // compute buf1
#pragma unroll
            for (int ks = 0; ks < 4; ks++) {
                uint32_t a[4], b[4];
                const int kb = ks * 32;
                ldsm_x4(buf1 + SWZ(rowA * 128 + kb + aCsel), a[0], a[1], a[2], a[3]);
                ldsm_x4(buf1 + X_OFF + SWZ(tokB * 128 + kb + bCsel),
                        b[0], b[1], b[2], b[3]);
                mma_16816(acc[0], a, b + 0);
                mma_16816(acc[1], a, b + 2);
            }
        }
    }

    // ---- epilogue: atomicAdd partials (2 deterministic contributors/elem) ----
    const int g = lane >> 2;
    const int t2 = (lane & 3) * 2;
    const int f0 = row_base + rg * 16 + g;
#pragma unroll
    for (int nt = 0; nt < 2; nt++) {
        const int tok = th * 16 + nt * 8 + t2;
        atomicAdd(&out[(size_t)tok * OUTF + f0],           acc[nt][0]);
        atomicAdd(&out[(size_t)(tok + 1) * OUTF + f0],     acc[nt][1]);
        atomicAdd(&out[(size_t)tok * OUTF + f0 + 8],       acc[nt][2]);
        atomicAdd(&out[(size_t)(tok + 1) * OUTF + f0 + 8], acc[nt][3]);
    }
}

// ---------------- launch ----------------
extern "C" void kernel_launch(void* const* d_in, const int* in_sizes, int n_in,
                              void* d_out, int out_size) {
    const float* x      = (const float*)d_in[0];
    const int*   weight = (const int*)d_in[1];
    const float* scales = (const float*)d_in[2];
    float*       out    = (float*)d_out;
    (void)in_sizes; (void)n_in; (void)out_size;

    prep_kernel<<<(TOKENS * INF + 255) / 256, 256>>>(x, scales, (float4*)out);
    qgemm_kernel<<<(OUTF / TILE_M) * KSPLIT, NTHR>>>(weight, out);
}